// round 13
// baseline (speedup 1.0000x reference)
#include <cuda_runtime.h>
#include <cuda_fp16.h>
#include <math.h>
#include <stdint.h>

#define B_   16
#define CLEN 4096
#define QLEN 512
#define H    256

// ---- scratch (device globals; allocation-free) ----
__device__ __align__(128) __half g_S [(size_t)B_*CLEN*QLEN];   // logits S (fp16)
__device__ __align__(128) __half g_P [(size_t)B_*CLEN*QLEN];   // probs fp16
__device__ __align__(128) __half g_ch[(size_t)B_*CLEN*H];      // c fp16
__device__ __align__(128) __half g_qsh[B_*QLEN*H];             // (q*w_cq) fp16
__device__ __align__(128) __half g_qt[B_*H*QLEN];              // q^T fp16 [b][d][j]
__device__ float g_u[B_*CLEN];
__device__ float g_v[B_*QLEN];
__device__ float g_m[B_*CLEN];
__device__ float g_bm[B_];
__device__ float g_Z[B_];
__device__ float g_part[B_*32*H];
__device__ float g_q2c[B_*H];

#define CPA16(s,g)  asm volatile("cp.async.cg.shared.global [%0], [%1], 16;\n" :: "r"(s), "l"(g))
#define CPCOMMIT()  asm volatile("cp.async.commit_group;\n")
#define CPWAIT0()   asm volatile("cp.async.wait_group 0;\n")
#define CPWAIT1()   asm volatile("cp.async.wait_group 1;\n")
#define CPWAIT2()   asm volatile("cp.async.wait_group 2;\n")

#define LDSM4(r0,r1,r2,r3,addr) \
    asm volatile("ldmatrix.sync.aligned.m8n8.x4.shared.b16 {%0,%1,%2,%3}, [%4];" \
        : "=r"(r0),"=r"(r1),"=r"(r2),"=r"(r3) : "r"(addr))

__device__ __forceinline__ void mma_f16(float* d, const uint32_t* a, const uint32_t* b){
    asm volatile("mma.sync.aligned.m16n8k16.row.col.f32.f16.f16.f32 "
        "{%0,%1,%2,%3}, {%4,%5,%6,%7}, {%8,%9}, {%0,%1,%2,%3};"
        : "+f"(d[0]),"+f"(d[1]),"+f"(d[2]),"+f"(d[3])
        : "r"(a[0]),"r"(a[1]),"r"(a[2]),"r"(a[3]), "r"(b[0]),"r"(b[1]));
}

// gemm1 tile geometry: CTA 128x128, BK=32, pitch 40 halves, 4 stages
#define PITCH   40
#define TILEB   10240u            // 128*40*2 bytes per operand per stage
#define BOFF    40960u            // B tiles start after 4 A stages
#define SMEMSZ  81920             // 2 ops * 4 stages * TILEB

// gemm2 tile geometry: CTA 128x256, BK=32, 4 stages
#define TILEB2A 10240u            // 128*40*2
#define TILEB2B 20480u            // 256*40*2
#define B2OFF   40960u            // after 4 A stages
#define SMEMSZ2 122880            // 40960 + 4*20480

// ---------------------------------------------------------------------------
// prep_uv (fused): warp-per-row.
// ---------------------------------------------------------------------------
__global__ __launch_bounds__(256) void prep_uv(
    const float* __restrict__ c, const float* __restrict__ q,
    const float* __restrict__ w_c, const float* __restrict__ b_c,
    const float* __restrict__ w_q, const float* __restrict__ b_q,
    const float* __restrict__ w_cq, const float* __restrict__ b_cq)
{
    int warp = (blockIdx.x * blockDim.x + threadIdx.x) >> 5;
    int lane = threadIdx.x & 31;
    if (warp < B_ * CLEN) {
        const float4* row = (const float4*)(c + (size_t)warp * H);
        uint2* dst = (uint2*)(g_ch + (size_t)warp * H);
        float s = 0.f;
        #pragma unroll
        for (int t = 0; t < 2; t++) {
            int idx = lane + t*32;
            float4 x = row[idx];
            float4 wv = ((const float4*)w_c)[idx];
            s += x.x*wv.x + x.y*wv.y + x.z*wv.z + x.w*wv.w;
            union { __half2 h2[2]; uint2 u; } tt;
            tt.h2[0] = __floats2half2_rn(x.x, x.y);
            tt.h2[1] = __floats2half2_rn(x.z, x.w);
            dst[idx] = tt.u;
        }
        #pragma unroll
        for (int o = 16; o; o >>= 1) s += __shfl_xor_sync(0xffffffffu, s, o);
        if (lane == 0) g_u[warp] = s + b_c[0];
    } else {
        int r = warp - B_ * CLEN;
        if (r < B_ * QLEN) {
            const float4* row = (const float4*)(q + (size_t)r * H);
            uint2* dst = (uint2*)(g_qsh + (size_t)r * H);
            float s = 0.f;
            #pragma unroll
            for (int t = 0; t < 2; t++) {
                int idx = lane + t*32;
                float4 x = row[idx];
                float4 wq = ((const float4*)w_q)[idx];
                float4 wm = ((const float4*)w_cq)[idx];
                s += x.x*wq.x + x.y*wq.y + x.z*wq.z + x.w*wq.w;
                union { __half2 h2[2]; uint2 u; } tt;
                tt.h2[0] = __floats2half2_rn(x.x*wm.x, x.y*wm.y);
                tt.h2[1] = __floats2half2_rn(x.z*wm.z, x.w*wm.w);
                dst[idx] = tt.u;
            }
            #pragma unroll
            for (int o = 16; o; o >>= 1) s += __shfl_xor_sync(0xffffffffu, s, o);
            if (lane == 0) g_v[r] = s + b_q[0] + b_cq[0];
        }
    }
}

// ---------------------------------------------------------------------------
// qtrans: q[b][j][d] fp32 -> g_qt[b][d][j] fp16
// ---------------------------------------------------------------------------
__global__ void qtrans_kernel(const float* __restrict__ q)
{
    __shared__ float tile[32][33];
    const int j0 = blockIdx.x * 32, d0 = blockIdx.y * 32, b = blockIdx.z;
    const int tx = threadIdx.x, ty = threadIdx.y;   // 32 x 8
    #pragma unroll
    for (int r = 0; r < 4; r++)
        tile[ty + 8*r][tx] = q[((size_t)b*QLEN + j0 + ty + 8*r)*H + d0 + tx];
    __syncthreads();
    #pragma unroll
    for (int r = 0; r < 4; r++) {
        int d = d0 + ty + 8*r, j = j0 + tx;
        g_qt[((size_t)b*H + d)*QLEN + j] = __float2half_rn(tile[tx][ty + 8*r]);
    }
}

// ---------------------------------------------------------------------------
// GEMM1 (fp16 mma, 512 thr, warp 32x32, 4-stage BK=32): S = c.(q*w_cq)^T + v
// ---------------------------------------------------------------------------
__global__ __launch_bounds__(512,2) void gemm1_f16()
{
    extern __shared__ __align__(128) char dsm[];
    const int b  = blockIdx.z, m0 = blockIdx.y*128, n0 = blockIdx.x*128;
    const int tid = threadIdx.x;
    const int lane = tid & 31, wid = tid >> 5;
    const int wm = wid >> 2, wn = wid & 3;
    const int gid = lane >> 2, tig = lane & 3;
    const int cr = tid >> 2;
    const int cc = (tid & 3) * 8;

    const __half* Ag = g_ch  + ((size_t)b*CLEN + m0 + cr)*H + cc;
    const __half* Bg = g_qsh + ((size_t)b*QLEN + n0 + cr)*H + cc;
    const uint32_t sbase = (uint32_t)__cvta_generic_to_shared(dsm);
    const uint32_t wOff = (uint32_t)(cr*PITCH + cc)*2u;

    const int rA = lane & 15, cA = (lane & 16) >> 1;
    const int rB = (lane & 7) + ((lane & 16) >> 1), cB = lane & 8;
    const uint32_t offA = (uint32_t)(rA*PITCH + cA)*2u;
    const uint32_t offB = (uint32_t)(rB*PITCH + cB)*2u;

    float acc[2][4][4];
    #pragma unroll
    for (int i = 0; i < 2; i++)
        #pragma unroll
        for (int j = 0; j < 4; j++)
            #pragma unroll
            for (int r = 0; r < 4; r++) acc[i][j][r] = 0.f;

    const int NIT = H/32;   // 8
    #pragma unroll
    for (int p = 0; p < 3; p++) {
        CPA16(sbase + p*TILEB + wOff,        Ag + p*32);
        CPA16(sbase + BOFF + p*TILEB + wOff, Bg + p*32);
        CPCOMMIT();
    }

    for (int i = 0; i < NIT; i++) {
        if (i < NIT-2)      { CPWAIT2(); }
        else if (i == NIT-2){ CPWAIT1(); }
        else                { CPWAIT0(); }
        __syncthreads();
        const int st = i & 3;
        const uint32_t aBase = sbase + st*TILEB + (uint32_t)(wm*32)*PITCH*2u + offA;
        const uint32_t bBase = sbase + BOFF + st*TILEB + (uint32_t)(wn*32)*PITCH*2u + offB;
        #pragma unroll
        for (int ks = 0; ks < 32; ks += 16) {
            uint32_t a[2][4], bf[4][2];
            #pragma unroll
            for (int mt = 0; mt < 2; mt++)
                LDSM4(a[mt][0], a[mt][1], a[mt][2], a[mt][3],
                      aBase + (uint32_t)(mt*16)*PITCH*2u + ks*2u);
            #pragma unroll
            for (int p = 0; p < 2; p++)
                LDSM4(bf[2*p][0], bf[2*p][1], bf[2*p+1][0], bf[2*p+1][1],
                      bBase + (uint32_t)(p*16)*PITCH*2u + ks*2u);
            #pragma unroll
            for (int mt = 0; mt < 2; mt++)
                #pragma unroll
                for (int nt = 0; nt < 4; nt++)
                    mma_f16(acc[mt][nt], a[mt], bf[nt]);
        }
        if (i + 3 < NIT) {
            const int kc = (i+3)*32, s2 = (i+3) & 3;
            CPA16(sbase + s2*TILEB + wOff,        Ag + kc);
            CPA16(sbase + BOFF + s2*TILEB + wOff, Bg + kc);
            CPCOMMIT();
        }
    }

    // epilogue: +v, write S fp16
    const float* vb = g_v + b*QLEN + n0 + wn*32;
    float2 vv[4];
    #pragma unroll
    for (int nt = 0; nt < 4; nt++) vv[nt] = *(const float2*)&vb[nt*8 + 2*tig];
    #pragma unroll
    for (int mt = 0; mt < 2; mt++)
        #pragma unroll
        for (int r = 0; r < 2; r++) {
            int row = m0 + wm*32 + mt*16 + gid + 8*r;
            __half2* p = (__half2*)(g_S + ((size_t)b*CLEN + row)*QLEN + n0 + wn*32);
            #pragma unroll
            for (int nt = 0; nt < 4; nt++)
                p[nt*4 + tig] = __floats2half2_rn(acc[mt][nt][2*r]   + vv[nt].x,
                                                  acc[mt][nt][2*r+1] + vv[nt].y);
        }
}

// ---------------------------------------------------------------------------
// softmax over j (512): read S fp16, write probs fp16; g_m = rowmax + u
// ---------------------------------------------------------------------------
__global__ __launch_bounds__(256) void softmax_kernel()
{
    int warp = (blockIdx.x * blockDim.x + threadIdx.x) >> 5;
    if (warp >= B_ * CLEN) return;
    int lane = threadIdx.x & 31;
    const __half2* row = (const __half2*)(g_S + (size_t)warp * QLEN);
    __half2* ph = (__half2*)(g_P + (size_t)warp * QLEN);

    float2 v[8];
    float mx = -3.402823466e38f;
    #pragma unroll
    for (int t = 0; t < 8; t++) {
        v[t] = __half22float2(row[lane + t*32]);
        mx = fmaxf(mx, fmaxf(v[t].x, v[t].y));
    }
    #pragma unroll
    for (int o = 16; o; o >>= 1) mx = fmaxf(mx, __shfl_xor_sync(0xffffffffu, mx, o));
    float s = 0.f;
    #pragma unroll
    for (int t = 0; t < 8; t++) {
        v[t].x = __expf(v[t].x - mx); v[t].y = __expf(v[t].y - mx);
        s += v[t].x + v[t].y;
    }
    #pragma unroll
    for (int o = 16; o; o >>= 1) s += __shfl_xor_sync(0xffffffffu, s, o);
    float inv = 1.f / s;
    #pragma unroll
    for (int t = 0; t < 8; t++)
        ph[lane + t*32] = __floats2half2_rn(v[t].x * inv, v[t].y * inv);
    if (lane == 0) g_m[warp] = mx + g_u[warp];
}

// ---------------------------------------------------------------------------
// q2c chain
// ---------------------------------------------------------------------------
__global__ __launch_bounds__(1024) void bmz_kernel()
{
    int b = blockIdx.x, tid = threadIdx.x;
    __shared__ float red[32];
    const float* m = g_m + b*CLEN;
    float mx = fmaxf(m[tid], fmaxf(m[tid+1024], fmaxf(m[tid+2048], m[tid+3072])));
    #pragma unroll
    for (int o = 16; o; o >>= 1) mx = fmaxf(mx, __shfl_xor_sync(0xffffffffu, mx, o));
    if ((tid & 31) == 0) red[tid >> 5] = mx;
    __syncthreads();
    mx = red[0];
    #pragma unroll
    for (int i = 1; i < 32; i++) mx = fmaxf(mx, red[i]);
    __syncthreads();
    float s = __expf(m[tid]-mx) + __expf(m[tid+1024]-mx)
            + __expf(m[tid+2048]-mx) + __expf(m[tid+3072]-mx);
    #pragma unroll
    for (int o = 16; o; o >>= 1) s += __shfl_xor_sync(0xffffffffu, s, o);
    if ((tid & 31) == 0) red[tid >> 5] = s;
    __syncthreads();
    if (tid == 0) {
        float Z = 0.f;
        #pragma unroll
        for (int i = 0; i < 32; i++) Z += red[i];
        g_bm[b] = mx; g_Z[b] = Z;
    }
}

__global__ __launch_bounds__(256) void q2c_part()
{
    const int b = blockIdx.y, p = blockIdx.x, tid = threadIdx.x;
    __shared__ float w[128];
    if (tid < 128) w[tid] = __expf(g_m[b*CLEN + p*128 + tid] - g_bm[b]);
    __syncthreads();
    const float invZ = 1.f / g_Z[b];
    const __half* cb = g_ch + ((size_t)b*CLEN + p*128)*H + tid;
    float acc = 0.f;
    #pragma unroll 8
    for (int i = 0; i < 128; i++) acc = fmaf(w[i], __half2float(cb[(size_t)i*H]), acc);
    g_part[(b*32 + p)*H + tid] = acc * invZ;
}

__global__ __launch_bounds__(256) void q2c_reduce()
{
    int b = blockIdx.x, d = threadIdx.x;
    float s = 0.f;
    #pragma unroll
    for (int p = 0; p < 32; p++) s += g_part[(b*32 + p)*H + d];
    g_q2c[b*H + d] = s;
}

// ---------------------------------------------------------------------------
// GEMM2 (fp16 mma, 512 thr, CTA 128x256, warp 32x64, 4-stage BK=32)
// c2q = P @ q with fused 4-section epilogue; c read as fp16 (g_ch)
// ---------------------------------------------------------------------------
__global__ __launch_bounds__(512,1) void gemm2_f16(float* __restrict__ out)
{
    extern __shared__ __align__(128) char dsm[];
    const int b  = blockIdx.y, m0 = blockIdx.x*128;
    const int tid = threadIdx.x;
    const int lane = tid & 31, wid = tid >> 5;
    const int wm = wid >> 2, wn = wid & 3;      // 4 x 4 warps; warp tile 32x64
    const int gid = lane >> 2, tig = lane & 3;
    const int cr = tid >> 2;                    // 0..127
    const int cc = (tid & 3) * 8;               // 0/8/16/24

    const __half* Ag  = g_P  + ((size_t)b*CLEN + m0 + cr)*QLEN + cc;
    const __half* Bg0 = g_qt + ((size_t)b*H + cr)*QLEN + cc;
    const __half* Bg1 = g_qt + ((size_t)b*H + cr + 128)*QLEN + cc;
    const uint32_t sbase = (uint32_t)__cvta_generic_to_shared(dsm);
    const uint32_t wA  = (uint32_t)(cr*PITCH + cc)*2u;
    const uint32_t wB0 = (uint32_t)(cr*PITCH + cc)*2u;
    const uint32_t wB1 = (uint32_t)((cr+128)*PITCH + cc)*2u;

    const int rA = lane & 15, cA = (lane & 16) >> 1;
    const int rB = (lane & 7) + ((lane & 16) >> 1), cB = lane & 8;
    const uint32_t offA = (uint32_t)(rA*PITCH + cA)*2u;
    const uint32_t offB = (uint32_t)(rB*PITCH + cB)*2u;

    float acc[2][8][4];
    #pragma unroll
    for (int i = 0; i < 2; i++)
        #pragma unroll
        for (int j = 0; j < 8; j++)
            #pragma unroll
            for (int r = 0; r < 4; r++) acc[i][j][r] = 0.f;

    const int NIT = QLEN/32;   // 16
    #pragma unroll
    for (int p = 0; p < 3; p++) {
        CPA16(sbase + p*TILEB2A + wA,          Ag  + p*32);
        CPA16(sbase + B2OFF + p*TILEB2B + wB0, Bg0 + p*32);
        CPA16(sbase + B2OFF + p*TILEB2B + wB1, Bg1 + p*32);
        CPCOMMIT();
    }

    for (int i = 0; i < NIT; i++) {
        if (i < NIT-2)      { CPWAIT2(); }
        else if (i == NIT-2){ CPWAIT1(); }
        else                { CPWAIT0(); }
        __syncthreads();
        const int st = i & 3;
        const uint32_t aBase = sbase + st*TILEB2A + (uint32_t)(wm*32)*PITCH*2u + offA;
        const uint32_t bBase = sbase + B2OFF + st*TILEB2B + (uint32_t)(wn*64)*PITCH*2u + offB;
        #pragma unroll
        for (int ks = 0; ks < 32; ks += 16) {
            uint32_t a[2][4], bf[8][2];
            #pragma unroll
            for (int mt = 0; mt < 2; mt++)
                LDSM4(a[mt][0], a[mt][1], a[mt][2], a[mt][3],
                      aBase + (uint32_t)(mt*16)*PITCH*2u + ks*2u);
            #pragma unroll
            for (int p = 0; p < 4; p++)
                LDSM4(bf[2*p][0], bf[2*p][1], bf[2*p+1][0], bf[2*p+1][1],
                      bBase + (uint32_t)(p*16)*PITCH*2u + ks*2u);
            #pragma unroll
            for (int mt = 0; mt < 2; mt++)
                #pragma unroll
                for (int nt = 0; nt < 8; nt++)
                    mma_f16(acc[mt][nt], a[mt], bf[nt]);
        }
        if (i + 3 < NIT) {
            const int kc = (i+3)*32, s2 = (i+3) & 3;
            CPA16(sbase + s2*TILEB2A + wA,          Ag  + kc);
            CPA16(sbase + B2OFF + s2*TILEB2B + wB0, Bg0 + kc);
            CPA16(sbase + B2OFF + s2*TILEB2B + wB1, Bg1 + kc);
            CPCOMMIT();
        }
    }

    // fused epilogue: out = [c | c2q | c*c2q | c*q2c], c from fp16 g_ch
    const int nbase = wn*64;
    float2 gv[8];
    #pragma unroll
    for (int nt = 0; nt < 8; nt++)
        gv[nt] = *(const float2*)&g_q2c[b*H + nbase + nt*8 + 2*tig];
    #pragma unroll
    for (int mt = 0; mt < 2; mt++)
        #pragma unroll
        for (int r = 0; r < 2; r++) {
            int row = m0 + wm*32 + mt*16 + gid + 8*r;
            const __half2* crow = (const __half2*)(g_ch + ((size_t)b*CLEN + row)*H);
            float* orow = out + ((size_t)b*CLEN + row)*(4*H);
            #pragma unroll
            for (int nt = 0; nt < 8; nt++) {
                int col = nbase + nt*8 + 2*tig;
                float2 cv = __half22float2(crow[col >> 1]);
                float2 av = make_float2(acc[mt][nt][2*r], acc[mt][nt][2*r+1]);
                *(float2*)&orow[col]       = cv;
                *(float2*)&orow[H + col]   = av;
                *(float2*)&orow[2*H + col] = make_float2(cv.x*av.x, cv.y*av.y);
                *(float2*)&orow[3*H + col] = make_float2(cv.x*gv[nt].x, cv.y*gv[nt].y);
            }
        }
}

// ---------------------------------------------------------------------------
extern "C" void kernel_launch(void* const* d_in, const int* in_sizes, int n_in,
                              void* d_out, int out_size)
{
    const float* c    = (const float*)d_in[0];
    const float* q    = (const float*)d_in[1];
    const float* w_c  = (const float*)d_in[2];
    const float* b_c  = (const float*)d_in[3];
    const float* w_q  = (const float*)d_in[4];
    const float* b_q  = (const float*)d_in[5];
    const float* w_cq = (const float*)d_in[6];
    const float* b_cq = (const float*)d_in[7];
    float* out = (float*)d_out;

    cudaFuncSetAttribute(gemm1_f16, cudaFuncAttributeMaxDynamicSharedMemorySize, SMEMSZ);
    cudaFuncSetAttribute(gemm2_f16, cudaFuncAttributeMaxDynamicSharedMemorySize, SMEMSZ2);

    {   // fused fp16 conversions + row dots
        int warps = B_*CLEN + B_*QLEN;
        prep_uv<<<(warps*32 + 255)/256, 256>>>(c, q, w_c, b_c, w_q, b_q, w_cq, b_cq);
    }
    {   // q^T fp16 for gemm2
        dim3 grid(QLEN/32, H/32, B_);
        qtrans_kernel<<<grid, dim3(32, 8)>>>(q);
    }
    {   // S = c.(q*w_cq)^T + v
        dim3 grid(QLEN/128, CLEN/128, B_);
        gemm1_f16<<<grid, 512, SMEMSZ>>>();
    }
    {   // row softmax -> fp16 probs
        int warps = B_*CLEN;
        softmax_kernel<<<(warps*32 + 255)/256, 256>>>();
    }
    bmz_kernel<<<B_, 1024>>>();
    {
        dim3 grid(32, B_);
        q2c_part<<<grid, 256>>>();
    }
    q2c_reduce<<<B_, 256>>>();
    {   // c2q + fused output (full-H N-tile)
        dim3 grid(CLEN/128, B_);
        gemm2_f16<<<grid, 512, SMEMSZ2>>>(out);
    }
}

// round 14
// speedup vs baseline: 1.0194x; 1.0194x over previous
#include <cuda_runtime.h>
#include <cuda_fp16.h>
#include <math.h>
#include <stdint.h>

#define B_   16
#define CLEN 4096
#define QLEN 512
#define H    256

// ---- scratch (device globals; allocation-free) ----
__device__ __align__(128) __half g_S [(size_t)B_*CLEN*QLEN];   // logits S (fp16)
__device__ __align__(128) __half g_P [(size_t)B_*CLEN*QLEN];   // probs fp16
__device__ __align__(128) __half g_ch[(size_t)B_*CLEN*H];      // c fp16
__device__ __align__(128) __half g_qsh[B_*QLEN*H];             // (q*w_cq) fp16
__device__ __align__(128) __half g_qt[B_*H*QLEN];              // q^T fp16 [b][d][j]
__device__ float g_u[B_*CLEN];
__device__ float g_v[B_*QLEN];
__device__ float g_m[B_*CLEN];
__device__ float g_bm[B_];
__device__ float g_Z[B_];
__device__ float g_part[B_*32*H];
__device__ float g_q2c[B_*H];

#define CPA16(s,g)  asm volatile("cp.async.cg.shared.global [%0], [%1], 16;\n" :: "r"(s), "l"(g))
#define CPCOMMIT()  asm volatile("cp.async.commit_group;\n")
#define CPWAIT0()   asm volatile("cp.async.wait_group 0;\n")
#define CPWAIT1()   asm volatile("cp.async.wait_group 1;\n")
#define CPWAIT2()   asm volatile("cp.async.wait_group 2;\n")

#define LDSM4(r0,r1,r2,r3,addr) \
    asm volatile("ldmatrix.sync.aligned.m8n8.x4.shared.b16 {%0,%1,%2,%3}, [%4];" \
        : "=r"(r0),"=r"(r1),"=r"(r2),"=r"(r3) : "r"(addr))

__device__ __forceinline__ void mma_f16(float* d, const uint32_t* a, const uint32_t* b){
    asm volatile("mma.sync.aligned.m16n8k16.row.col.f32.f16.f16.f32 "
        "{%0,%1,%2,%3}, {%4,%5,%6,%7}, {%8,%9}, {%0,%1,%2,%3};"
        : "+f"(d[0]),"+f"(d[1]),"+f"(d[2]),"+f"(d[3])
        : "r"(a[0]),"r"(a[1]),"r"(a[2]),"r"(a[3]), "r"(b[0]),"r"(b[1]));
}

// tile geometry: CTA 128x128, BK=32, pitch 40 halves, 4 stages
#define PITCH   40
#define TILEB   10240u            // 128*40*2 bytes per operand per stage
#define BOFF    40960u            // B tiles start after 4 A stages
#define SMEMSZ  81920             // 2 ops * 4 stages * TILEB

// ---------------------------------------------------------------------------
// prep_uv (fused): warp-per-row.
//  c rows:  g_ch = fp16(c); u = c.w_c + b_c
//  q rows:  g_qsh = fp16(q*w_cq); v = q.w_q + b_q + b_cq
// ---------------------------------------------------------------------------
__global__ __launch_bounds__(256) void prep_uv(
    const float* __restrict__ c, const float* __restrict__ q,
    const float* __restrict__ w_c, const float* __restrict__ b_c,
    const float* __restrict__ w_q, const float* __restrict__ b_q,
    const float* __restrict__ w_cq, const float* __restrict__ b_cq)
{
    int warp = (blockIdx.x * blockDim.x + threadIdx.x) >> 5;
    int lane = threadIdx.x & 31;
    if (warp < B_ * CLEN) {
        const float4* row = (const float4*)(c + (size_t)warp * H);
        uint2* dst = (uint2*)(g_ch + (size_t)warp * H);
        float s = 0.f;
        #pragma unroll
        for (int t = 0; t < 2; t++) {
            int idx = lane + t*32;
            float4 x = row[idx];
            float4 wv = ((const float4*)w_c)[idx];
            s += x.x*wv.x + x.y*wv.y + x.z*wv.z + x.w*wv.w;
            union { __half2 h2[2]; uint2 u; } tt;
            tt.h2[0] = __floats2half2_rn(x.x, x.y);
            tt.h2[1] = __floats2half2_rn(x.z, x.w);
            dst[idx] = tt.u;
        }
        #pragma unroll
        for (int o = 16; o; o >>= 1) s += __shfl_xor_sync(0xffffffffu, s, o);
        if (lane == 0) g_u[warp] = s + b_c[0];
    } else {
        int r = warp - B_ * CLEN;
        if (r < B_ * QLEN) {
            const float4* row = (const float4*)(q + (size_t)r * H);
            uint2* dst = (uint2*)(g_qsh + (size_t)r * H);
            float s = 0.f;
            #pragma unroll
            for (int t = 0; t < 2; t++) {
                int idx = lane + t*32;
                float4 x = row[idx];
                float4 wq = ((const float4*)w_q)[idx];
                float4 wm = ((const float4*)w_cq)[idx];
                s += x.x*wq.x + x.y*wq.y + x.z*wq.z + x.w*wq.w;
                union { __half2 h2[2]; uint2 u; } tt;
                tt.h2[0] = __floats2half2_rn(x.x*wm.x, x.y*wm.y);
                tt.h2[1] = __floats2half2_rn(x.z*wm.z, x.w*wm.w);
                dst[idx] = tt.u;
            }
            #pragma unroll
            for (int o = 16; o; o >>= 1) s += __shfl_xor_sync(0xffffffffu, s, o);
            if (lane == 0) g_v[r] = s + b_q[0] + b_cq[0];
        }
    }
}

// ---------------------------------------------------------------------------
// qtrans: q[b][j][d] fp32 -> g_qt[b][d][j] fp16
// ---------------------------------------------------------------------------
__global__ void qtrans_kernel(const float* __restrict__ q)
{
    __shared__ float tile[32][33];
    const int j0 = blockIdx.x * 32, d0 = blockIdx.y * 32, b = blockIdx.z;
    const int tx = threadIdx.x, ty = threadIdx.y;   // 32 x 8
    #pragma unroll
    for (int r = 0; r < 4; r++)
        tile[ty + 8*r][tx] = q[((size_t)b*QLEN + j0 + ty + 8*r)*H + d0 + tx];
    __syncthreads();
    #pragma unroll
    for (int r = 0; r < 4; r++) {
        int d = d0 + ty + 8*r, j = j0 + tx;
        g_qt[((size_t)b*H + d)*QLEN + j] = __float2half_rn(tile[tx][ty + 8*r]);
    }
}

// ---------------------------------------------------------------------------
// GEMM1 (fp16 mma, 512 thr, warp 32x32, 4-stage BK=32): S = c.(q*w_cq)^T + v
// epilogue writes fp16 S
// ---------------------------------------------------------------------------
__global__ __launch_bounds__(512,2) void gemm1_f16()
{
    extern __shared__ __align__(128) char dsm[];
    const int b  = blockIdx.z, m0 = blockIdx.y*128, n0 = blockIdx.x*128;
    const int tid = threadIdx.x;
    const int lane = tid & 31, wid = tid >> 5;
    const int wm = wid >> 2, wn = wid & 3;      // 4 x 4 warps, warp tile 32x32
    const int gid = lane >> 2, tig = lane & 3;
    const int cr = tid >> 2;                    // copy row 0..127
    const int cc = (tid & 3) * 8;               // half offset 0/8/16/24

    const __half* Ag = g_ch  + ((size_t)b*CLEN + m0 + cr)*H + cc;
    const __half* Bg = g_qsh + ((size_t)b*QLEN + n0 + cr)*H + cc;
    const uint32_t sbase = (uint32_t)__cvta_generic_to_shared(dsm);
    const uint32_t wOff = (uint32_t)(cr*PITCH + cc)*2u;

    const int rA = lane & 15, cA = (lane & 16) >> 1;
    const int rB = (lane & 7) + ((lane & 16) >> 1), cB = lane & 8;
    const uint32_t offA = (uint32_t)(rA*PITCH + cA)*2u;
    const uint32_t offB = (uint32_t)(rB*PITCH + cB)*2u;

    float acc[2][4][4];
    #pragma unroll
    for (int i = 0; i < 2; i++)
        #pragma unroll
        for (int j = 0; j < 4; j++)
            #pragma unroll
            for (int r = 0; r < 4; r++) acc[i][j][r] = 0.f;

    const int NIT = H/32;   // 8
    #pragma unroll
    for (int p = 0; p < 3; p++) {
        CPA16(sbase + p*TILEB + wOff,        Ag + p*32);
        CPA16(sbase + BOFF + p*TILEB + wOff, Bg + p*32);
        CPCOMMIT();
    }

    for (int i = 0; i < NIT; i++) {
        if (i < NIT-2)      { CPWAIT2(); }
        else if (i == NIT-2){ CPWAIT1(); }
        else                { CPWAIT0(); }
        __syncthreads();
        const int st = i & 3;
        const uint32_t aBase = sbase + st*TILEB + (uint32_t)(wm*32)*PITCH*2u + offA;
        const uint32_t bBase = sbase + BOFF + st*TILEB + (uint32_t)(wn*32)*PITCH*2u + offB;
        #pragma unroll
        for (int ks = 0; ks < 32; ks += 16) {
            uint32_t a[2][4], bf[4][2];
            #pragma unroll
            for (int mt = 0; mt < 2; mt++)
                LDSM4(a[mt][0], a[mt][1], a[mt][2], a[mt][3],
                      aBase + (uint32_t)(mt*16)*PITCH*2u + ks*2u);
            #pragma unroll
            for (int p = 0; p < 2; p++)
                LDSM4(bf[2*p][0], bf[2*p][1], bf[2*p+1][0], bf[2*p+1][1],
                      bBase + (uint32_t)(p*16)*PITCH*2u + ks*2u);
            #pragma unroll
            for (int mt = 0; mt < 2; mt++)
                #pragma unroll
                for (int nt = 0; nt < 4; nt++)
                    mma_f16(acc[mt][nt], a[mt], bf[nt]);
        }
        if (i + 3 < NIT) {
            const int kc = (i+3)*32, s2 = (i+3) & 3;
            CPA16(sbase + s2*TILEB + wOff,        Ag + kc);
            CPA16(sbase + BOFF + s2*TILEB + wOff, Bg + kc);
            CPCOMMIT();
        }
    }

    // epilogue: +v, write S fp16
    const float* vb = g_v + b*QLEN + n0 + wn*32;
    float2 vv[4];
    #pragma unroll
    for (int nt = 0; nt < 4; nt++) vv[nt] = *(const float2*)&vb[nt*8 + 2*tig];
    #pragma unroll
    for (int mt = 0; mt < 2; mt++)
        #pragma unroll
        for (int r = 0; r < 2; r++) {
            int row = m0 + wm*32 + mt*16 + gid + 8*r;
            __half2* p = (__half2*)(g_S + ((size_t)b*CLEN + row)*QLEN + n0 + wn*32);
            #pragma unroll
            for (int nt = 0; nt < 4; nt++)
                p[nt*4 + tig] = __floats2half2_rn(acc[mt][nt][2*r]   + vv[nt].x,
                                                  acc[mt][nt][2*r+1] + vv[nt].y);
        }
}

// ---------------------------------------------------------------------------
// softmax over j (512): read S fp16, write probs fp16; g_m = rowmax + u
// ---------------------------------------------------------------------------
__global__ __launch_bounds__(256) void softmax_kernel()
{
    int warp = (blockIdx.x * blockDim.x + threadIdx.x) >> 5;
    if (warp >= B_ * CLEN) return;
    int lane = threadIdx.x & 31;
    const __half2* row = (const __half2*)(g_S + (size_t)warp * QLEN);
    __half2* ph = (__half2*)(g_P + (size_t)warp * QLEN);

    float2 v[8];
    float mx = -3.402823466e38f;
    #pragma unroll
    for (int t = 0; t < 8; t++) {
        v[t] = __half22float2(row[lane + t*32]);
        mx = fmaxf(mx, fmaxf(v[t].x, v[t].y));
    }
    #pragma unroll
    for (int o = 16; o; o >>= 1) mx = fmaxf(mx, __shfl_xor_sync(0xffffffffu, mx, o));
    float s = 0.f;
    #pragma unroll
    for (int t = 0; t < 8; t++) {
        v[t].x = __expf(v[t].x - mx); v[t].y = __expf(v[t].y - mx);
        s += v[t].x + v[t].y;
    }
    #pragma unroll
    for (int o = 16; o; o >>= 1) s += __shfl_xor_sync(0xffffffffu, s, o);
    float inv = 1.f / s;
    #pragma unroll
    for (int t = 0; t < 8; t++)
        ph[lane + t*32] = __floats2half2_rn(v[t].x * inv, v[t].y * inv);
    if (lane == 0) g_m[warp] = mx + g_u[warp];
}

// ---------------------------------------------------------------------------
// q2c chain
// ---------------------------------------------------------------------------
__global__ __launch_bounds__(1024) void bmz_kernel()
{
    int b = blockIdx.x, tid = threadIdx.x;
    __shared__ float red[32];
    const float* m = g_m + b*CLEN;
    float mx = fmaxf(m[tid], fmaxf(m[tid+1024], fmaxf(m[tid+2048], m[tid+3072])));
    #pragma unroll
    for (int o = 16; o; o >>= 1) mx = fmaxf(mx, __shfl_xor_sync(0xffffffffu, mx, o));
    if ((tid & 31) == 0) red[tid >> 5] = mx;
    __syncthreads();
    mx = red[0];
    #pragma unroll
    for (int i = 1; i < 32; i++) mx = fmaxf(mx, red[i]);
    __syncthreads();
    float s = __expf(m[tid]-mx) + __expf(m[tid+1024]-mx)
            + __expf(m[tid+2048]-mx) + __expf(m[tid+3072]-mx);
    #pragma unroll
    for (int o = 16; o; o >>= 1) s += __shfl_xor_sync(0xffffffffu, s, o);
    if ((tid & 31) == 0) red[tid >> 5] = s;
    __syncthreads();
    if (tid == 0) {
        float Z = 0.f;
        #pragma unroll
        for (int i = 0; i < 32; i++) Z += red[i];
        g_bm[b] = mx; g_Z[b] = Z;
    }
}

__global__ __launch_bounds__(256) void q2c_part()
{
    const int b = blockIdx.y, p = blockIdx.x, tid = threadIdx.x;
    __shared__ float w[128];
    if (tid < 128) w[tid] = __expf(g_m[b*CLEN + p*128 + tid] - g_bm[b]);
    __syncthreads();
    const float invZ = 1.f / g_Z[b];
    const __half* cb = g_ch + ((size_t)b*CLEN + p*128)*H + tid;
    float acc = 0.f;
    #pragma unroll 8
    for (int i = 0; i < 128; i++) acc = fmaf(w[i], __half2float(cb[(size_t)i*H]), acc);
    g_part[(b*32 + p)*H + tid] = acc * invZ;
}

__global__ __launch_bounds__(256) void q2c_reduce()
{
    int b = blockIdx.x, d = threadIdx.x;
    float s = 0.f;
    #pragma unroll
    for (int p = 0; p < 32; p++) s += g_part[(b*32 + p)*H + d];
    g_q2c[b*H + d] = s;
}

// ---------------------------------------------------------------------------
// GEMM2 (fp16 mma + ldmatrix + 4-stage BK=32, 256 thr, CTA 128x128, occ 2):
// c2q = P @ q + fused epilogue; c read as fp16 (g_ch)
// ---------------------------------------------------------------------------
__global__ __launch_bounds__(256,2) void gemm2_f16(float* __restrict__ out)
{
    extern __shared__ __align__(128) char dsm[];
    const int b  = blockIdx.z, m0 = blockIdx.y*128, n0 = blockIdx.x*128;
    const int tid = threadIdx.x;
    const int lane = tid & 31, wid = tid >> 5;
    const int wm = wid >> 2, wn = wid & 3;
    const int gid = lane >> 2, tig = lane & 3;
    const int cr = tid >> 1;
    const int cc = (tid & 1) * 16;

    const __half* Ag = g_P  + ((size_t)b*CLEN + m0 + cr)*QLEN + cc;
    const __half* Bg = g_qt + ((size_t)b*H    + n0 + cr)*QLEN + cc;
    const uint32_t sbase = (uint32_t)__cvta_generic_to_shared(dsm);
    const uint32_t wOff = (uint32_t)(cr*PITCH + cc)*2u;

    const int rA = lane & 15, cA = (lane & 16) >> 1;
    const int rB = (lane & 7) + ((lane & 16) >> 1), cB = lane & 8;
    const uint32_t offA = (uint32_t)(rA*PITCH + cA)*2u;
    const uint32_t offB = (uint32_t)(rB*PITCH + cB)*2u;

    float acc[4][4][4];
    #pragma unroll
    for (int i = 0; i < 4; i++)
        #pragma unroll
        for (int j = 0; j < 4; j++)
            #pragma unroll
            for (int r = 0; r < 4; r++) acc[i][j][r] = 0.f;

    const int NIT = QLEN/32;   // 16
    #pragma unroll
    for (int p = 0; p < 3; p++) {
        const uint32_t sa = sbase + p*TILEB + wOff;
        const uint32_t sb = sbase + BOFF + p*TILEB + wOff;
        CPA16(sa, Ag + p*32); CPA16(sa + 16u, Ag + p*32 + 8);
        CPA16(sb, Bg + p*32); CPA16(sb + 16u, Bg + p*32 + 8);
        CPCOMMIT();
    }

    for (int i = 0; i < NIT; i++) {
        if (i < NIT-2)      { CPWAIT2(); }
        else if (i == NIT-2){ CPWAIT1(); }
        else                { CPWAIT0(); }
        __syncthreads();
        const int st = i & 3;
        const uint32_t aBase = sbase + st*TILEB + (uint32_t)(wm*64)*PITCH*2u + offA;
        const uint32_t bBase = sbase + BOFF + st*TILEB + (uint32_t)(wn*32)*PITCH*2u + offB;
        #pragma unroll
        for (int ks = 0; ks < 32; ks += 16) {
            uint32_t a[4][4], bf[4][2];
            #pragma unroll
            for (int mt = 0; mt < 4; mt++)
                LDSM4(a[mt][0], a[mt][1], a[mt][2], a[mt][3],
                      aBase + (uint32_t)(mt*16)*PITCH*2u + ks*2u);
            #pragma unroll
            for (int p = 0; p < 2; p++)
                LDSM4(bf[2*p][0], bf[2*p][1], bf[2*p+1][0], bf[2*p+1][1],
                      bBase + (uint32_t)(p*16)*PITCH*2u + ks*2u);
            #pragma unroll
            for (int mt = 0; mt < 4; mt++)
                #pragma unroll
                for (int nt = 0; nt < 4; nt++)
                    mma_f16(acc[mt][nt], a[mt], bf[nt]);
        }
        if (i + 3 < NIT) {
            const int kc = (i+3)*32, s2 = (i+3) & 3;
            const uint32_t sa = sbase + s2*TILEB + wOff;
            const uint32_t sb = sbase + BOFF + s2*TILEB + wOff;
            CPA16(sa, Ag + kc); CPA16(sa + 16u, Ag + kc + 8);
            CPA16(sb, Bg + kc); CPA16(sb + 16u, Bg + kc + 8);
            CPCOMMIT();
        }
    }

    // fused epilogue: out = [c | c2q | c*c2q | c*q2c], c from fp16 g_ch
    const int nbase = n0 + wn*32;
    float2 gv[4];
    #pragma unroll
    for (int nt = 0; nt < 4; nt++)
        gv[nt] = *(const float2*)&g_q2c[b*H + nbase + nt*8 + 2*tig];
    #pragma unroll
    for (int mt = 0; mt < 4; mt++)
        #pragma unroll
        for (int r = 0; r < 2; r++) {
            int row = m0 + wm*64 + mt*16 + gid + 8*r;
            const __half2* crow = (const __half2*)(g_ch + ((size_t)b*CLEN + row)*H);
            float* orow = out + ((size_t)b*CLEN + row)*(4*H);
            #pragma unroll
            for (int nt = 0; nt < 4; nt++) {
                int col = nbase + nt*8 + 2*tig;
                float2 cv = __half22float2(crow[col >> 1]);
                float2 av = make_float2(acc[mt][nt][2*r], acc[mt][nt][2*r+1]);
                *(float2*)&orow[col]       = cv;
                *(float2*)&orow[H + col]   = av;
                *(float2*)&orow[2*H + col] = make_float2(cv.x*av.x, cv.y*av.y);
                *(float2*)&orow[3*H + col] = make_float2(cv.x*gv[nt].x, cv.y*gv[nt].y);
            }
        }
}

// ---------------------------------------------------------------------------
extern "C" void kernel_launch(void* const* d_in, const int* in_sizes, int n_in,
                              void* d_out, int out_size)
{
    const float* c    = (const float*)d_in[0];
    const float* q    = (const float*)d_in[1];
    const float* w_c  = (const float*)d_in[2];
    const float* b_c  = (const float*)d_in[3];
    const float* w_q  = (const float*)d_in[4];
    const float* b_q  = (const float*)d_in[5];
    const float* w_cq = (const float*)d_in[6];
    const float* b_cq = (const float*)d_in[7];
    float* out = (float*)d_out;

    cudaFuncSetAttribute(gemm1_f16, cudaFuncAttributeMaxDynamicSharedMemorySize, SMEMSZ);
    cudaFuncSetAttribute(gemm2_f16, cudaFuncAttributeMaxDynamicSharedMemorySize, SMEMSZ);

    {   // fused fp16 conversions + row dots
        int warps = B_*CLEN + B_*QLEN;
        prep_uv<<<(warps*32 + 255)/256, 256>>>(c, q, w_c, b_c, w_q, b_q, w_cq, b_cq);
    }
    {   // q^T fp16 for gemm2
        dim3 grid(QLEN/32, H/32, B_);
        qtrans_kernel<<<grid, dim3(32, 8)>>>(q);
    }
    {   // S = c.(q*w_cq)^T + v
        dim3 grid(QLEN/128, CLEN/128, B_);
        gemm1_f16<<<grid, 512, SMEMSZ>>>();
    }
    {   // row softmax -> fp16 probs
        int warps = B_*CLEN;
        softmax_kernel<<<(warps*32 + 255)/256, 256>>>();
    }
    bmz_kernel<<<B_, 1024>>>();
    {
        dim3 grid(32, B_);
        q2c_part<<<grid, 256>>>();
    }
    q2c_reduce<<<B_, 256>>>();
    {   // c2q + fused output (128x128 tiles, occupancy 2)
        dim3 grid(H/128, CLEN/128, B_);
        gemm2_f16<<<grid, 256, SMEMSZ>>>(out);
    }
}

// round 16
// speedup vs baseline: 1.0454x; 1.0255x over previous
#include <cuda_runtime.h>
#include <cuda_fp16.h>
#include <math.h>
#include <stdint.h>

#define B_   16
#define CLEN 4096
#define QLEN 512
#define H    256

// ---- scratch (device globals; allocation-free) ----
__device__ __align__(128) __half g_S [(size_t)B_*CLEN*QLEN];   // logits S (fp16)
__device__ __align__(128) __half g_P [(size_t)B_*CLEN*QLEN];   // probs fp16
__device__ __align__(128) __half g_ch[(size_t)B_*CLEN*H];      // c fp16
__device__ __align__(128) __half g_qsh[B_*QLEN*H];             // (q*w_cq) fp16
__device__ __align__(128) __half g_qt[B_*H*QLEN];              // q^T fp16 [b][d][j]
__device__ float g_u[B_*CLEN];
__device__ float g_v[B_*QLEN];
__device__ float g_m[B_*CLEN];
__device__ float g_bm[B_];
__device__ float g_Z[B_];
__device__ float g_part[B_*32*H];
__device__ float g_q2c[B_*H];

#define CPA16(s,g)  asm volatile("cp.async.cg.shared.global [%0], [%1], 16;\n" :: "r"(s), "l"(g))
#define CPCOMMIT()  asm volatile("cp.async.commit_group;\n")
#define CPWAIT0()   asm volatile("cp.async.wait_group 0;\n")
#define CPWAIT1()   asm volatile("cp.async.wait_group 1;\n")
#define CPWAIT2()   asm volatile("cp.async.wait_group 2;\n")

#define LDSM4(r0,r1,r2,r3,addr) \
    asm volatile("ldmatrix.sync.aligned.m8n8.x4.shared.b16 {%0,%1,%2,%3}, [%4];" \
        : "=r"(r0),"=r"(r1),"=r"(r2),"=r"(r3) : "r"(addr))

// streaming (evict-first) 8-byte store: output is write-once, keep L2 for P/c/S
#define STGCS2(ptr, x, y) \
    asm volatile("st.global.cs.v2.f32 [%0], {%1,%2};" :: "l"(ptr), "f"(x), "f"(y) : "memory")

__device__ __forceinline__ void mma_f16(float* d, const uint32_t* a, const uint32_t* b){
    asm volatile("mma.sync.aligned.m16n8k16.row.col.f32.f16.f16.f32 "
        "{%0,%1,%2,%3}, {%4,%5,%6,%7}, {%8,%9}, {%0,%1,%2,%3};"
        : "+f"(d[0]),"+f"(d[1]),"+f"(d[2]),"+f"(d[3])
        : "r"(a[0]),"r"(a[1]),"r"(a[2]),"r"(a[3]), "r"(b[0]),"r"(b[1]));
}

// tile geometry: CTA 128x128, BK=32, pitch 40 halves, 4 stages
#define PITCH   40
#define TILEB   10240u            // 128*40*2 bytes per operand per stage
#define BOFF    40960u            // B tiles start after 4 A stages
#define SMEMSZ  81920             // 2 ops * 4 stages * TILEB

// ---------------------------------------------------------------------------
// prep_uv (fused): warp-per-row.
//  c rows:  g_ch = fp16(c); u = c.w_c + b_c
//  q rows:  g_qsh = fp16(q*w_cq); v = q.w_q + b_q + b_cq
// ---------------------------------------------------------------------------
__global__ __launch_bounds__(256) void prep_uv(
    const float* __restrict__ c, const float* __restrict__ q,
    const float* __restrict__ w_c, const float* __restrict__ b_c,
    const float* __restrict__ w_q, const float* __restrict__ b_q,
    const float* __restrict__ w_cq, const float* __restrict__ b_cq)
{
    int warp = (blockIdx.x * blockDim.x + threadIdx.x) >> 5;
    int lane = threadIdx.x & 31;
    if (warp < B_ * CLEN) {
        const float4* row = (const float4*)(c + (size_t)warp * H);
        uint2* dst = (uint2*)(g_ch + (size_t)warp * H);
        float s = 0.f;
        #pragma unroll
        for (int t = 0; t < 2; t++) {
            int idx = lane + t*32;
            float4 x = row[idx];
            float4 wv = ((const float4*)w_c)[idx];
            s += x.x*wv.x + x.y*wv.y + x.z*wv.z + x.w*wv.w;
            union { __half2 h2[2]; uint2 u; } tt;
            tt.h2[0] = __floats2half2_rn(x.x, x.y);
            tt.h2[1] = __floats2half2_rn(x.z, x.w);
            dst[idx] = tt.u;
        }
        #pragma unroll
        for (int o = 16; o; o >>= 1) s += __shfl_xor_sync(0xffffffffu, s, o);
        if (lane == 0) g_u[warp] = s + b_c[0];
    } else {
        int r = warp - B_ * CLEN;
        if (r < B_ * QLEN) {
            const float4* row = (const float4*)(q + (size_t)r * H);
            uint2* dst = (uint2*)(g_qsh + (size_t)r * H);
            float s = 0.f;
            #pragma unroll
            for (int t = 0; t < 2; t++) {
                int idx = lane + t*32;
                float4 x = row[idx];
                float4 wq = ((const float4*)w_q)[idx];
                float4 wm = ((const float4*)w_cq)[idx];
                s += x.x*wq.x + x.y*wq.y + x.z*wq.z + x.w*wq.w;
                union { __half2 h2[2]; uint2 u; } tt;
                tt.h2[0] = __floats2half2_rn(x.x*wm.x, x.y*wm.y);
                tt.h2[1] = __floats2half2_rn(x.z*wm.z, x.w*wm.w);
                dst[idx] = tt.u;
            }
            #pragma unroll
            for (int o = 16; o; o >>= 1) s += __shfl_xor_sync(0xffffffffu, s, o);
            if (lane == 0) g_v[r] = s + b_q[0] + b_cq[0];
        }
    }
}

// ---------------------------------------------------------------------------
// qtrans: q[b][j][d] fp32 -> g_qt[b][d][j] fp16
// ---------------------------------------------------------------------------
__global__ void qtrans_kernel(const float* __restrict__ q)
{
    __shared__ float tile[32][33];
    const int j0 = blockIdx.x * 32, d0 = blockIdx.y * 32, b = blockIdx.z;
    const int tx = threadIdx.x, ty = threadIdx.y;   // 32 x 8
    #pragma unroll
    for (int r = 0; r < 4; r++)
        tile[ty + 8*r][tx] = q[((size_t)b*QLEN + j0 + ty + 8*r)*H + d0 + tx];
    __syncthreads();
    #pragma unroll
    for (int r = 0; r < 4; r++) {
        int d = d0 + ty + 8*r, j = j0 + tx;
        g_qt[((size_t)b*H + d)*QLEN + j] = __float2half_rn(tile[tx][ty + 8*r]);
    }
}

// ---------------------------------------------------------------------------
// GEMM1 (fp16 mma, 512 thr, warp 32x32, 4-stage BK=32): S = c.(q*w_cq)^T + v
// epilogue writes fp16 S
// ---------------------------------------------------------------------------
__global__ __launch_bounds__(512,2) void gemm1_f16()
{
    extern __shared__ __align__(128) char dsm[];
    const int b  = blockIdx.z, m0 = blockIdx.y*128, n0 = blockIdx.x*128;
    const int tid = threadIdx.x;
    const int lane = tid & 31, wid = tid >> 5;
    const int wm = wid >> 2, wn = wid & 3;      // 4 x 4 warps, warp tile 32x32
    const int gid = lane >> 2, tig = lane & 3;
    const int cr = tid >> 2;                    // copy row 0..127
    const int cc = (tid & 3) * 8;               // half offset 0/8/16/24

    const __half* Ag = g_ch  + ((size_t)b*CLEN + m0 + cr)*H + cc;
    const __half* Bg = g_qsh + ((size_t)b*QLEN + n0 + cr)*H + cc;
    const uint32_t sbase = (uint32_t)__cvta_generic_to_shared(dsm);
    const uint32_t wOff = (uint32_t)(cr*PITCH + cc)*2u;

    const int rA = lane & 15, cA = (lane & 16) >> 1;
    const int rB = (lane & 7) + ((lane & 16) >> 1), cB = lane & 8;
    const uint32_t offA = (uint32_t)(rA*PITCH + cA)*2u;
    const uint32_t offB = (uint32_t)(rB*PITCH + cB)*2u;

    float acc[2][4][4];
    #pragma unroll
    for (int i = 0; i < 2; i++)
        #pragma unroll
        for (int j = 0; j < 4; j++)
            #pragma unroll
            for (int r = 0; r < 4; r++) acc[i][j][r] = 0.f;

    const int NIT = H/32;   // 8
    #pragma unroll
    for (int p = 0; p < 3; p++) {
        CPA16(sbase + p*TILEB + wOff,        Ag + p*32);
        CPA16(sbase + BOFF + p*TILEB + wOff, Bg + p*32);
        CPCOMMIT();
    }

    for (int i = 0; i < NIT; i++) {
        if (i < NIT-2)      { CPWAIT2(); }
        else if (i == NIT-2){ CPWAIT1(); }
        else                { CPWAIT0(); }
        __syncthreads();
        const int st = i & 3;
        const uint32_t aBase = sbase + st*TILEB + (uint32_t)(wm*32)*PITCH*2u + offA;
        const uint32_t bBase = sbase + BOFF + st*TILEB + (uint32_t)(wn*32)*PITCH*2u + offB;
        #pragma unroll
        for (int ks = 0; ks < 32; ks += 16) {
            uint32_t a[2][4], bf[4][2];
            #pragma unroll
            for (int mt = 0; mt < 2; mt++)
                LDSM4(a[mt][0], a[mt][1], a[mt][2], a[mt][3],
                      aBase + (uint32_t)(mt*16)*PITCH*2u + ks*2u);
            #pragma unroll
            for (int p = 0; p < 2; p++)
                LDSM4(bf[2*p][0], bf[2*p][1], bf[2*p+1][0], bf[2*p+1][1],
                      bBase + (uint32_t)(p*16)*PITCH*2u + ks*2u);
            #pragma unroll
            for (int mt = 0; mt < 2; mt++)
                #pragma unroll
                for (int nt = 0; nt < 4; nt++)
                    mma_f16(acc[mt][nt], a[mt], bf[nt]);
        }
        if (i + 3 < NIT) {
            const int kc = (i+3)*32, s2 = (i+3) & 3;
            CPA16(sbase + s2*TILEB + wOff,        Ag + kc);
            CPA16(sbase + BOFF + s2*TILEB + wOff, Bg + kc);
            CPCOMMIT();
        }
    }

    // epilogue: +v, write S fp16
    const float* vb = g_v + b*QLEN + n0 + wn*32;
    float2 vv[4];
    #pragma unroll
    for (int nt = 0; nt < 4; nt++) vv[nt] = *(const float2*)&vb[nt*8 + 2*tig];
    #pragma unroll
    for (int mt = 0; mt < 2; mt++)
        #pragma unroll
        for (int r = 0; r < 2; r++) {
            int row = m0 + wm*32 + mt*16 + gid + 8*r;
            __half2* p = (__half2*)(g_S + ((size_t)b*CLEN + row)*QLEN + n0 + wn*32);
            #pragma unroll
            for (int nt = 0; nt < 4; nt++)
                p[nt*4 + tig] = __floats2half2_rn(acc[mt][nt][2*r]   + vv[nt].x,
                                                  acc[mt][nt][2*r+1] + vv[nt].y);
        }
}

// ---------------------------------------------------------------------------
// softmax over j (512): read S fp16, write probs fp16; g_m = rowmax + u
// ---------------------------------------------------------------------------
__global__ __launch_bounds__(256) void softmax_kernel()
{
    int warp = (blockIdx.x * blockDim.x + threadIdx.x) >> 5;
    if (warp >= B_ * CLEN) return;
    int lane = threadIdx.x & 31;
    const __half2* row = (const __half2*)(g_S + (size_t)warp * QLEN);
    __half2* ph = (__half2*)(g_P + (size_t)warp * QLEN);

    float2 v[8];
    float mx = -3.402823466e38f;
    #pragma unroll
    for (int t = 0; t < 8; t++) {
        v[t] = __half22float2(row[lane + t*32]);
        mx = fmaxf(mx, fmaxf(v[t].x, v[t].y));
    }
    #pragma unroll
    for (int o = 16; o; o >>= 1) mx = fmaxf(mx, __shfl_xor_sync(0xffffffffu, mx, o));
    float s = 0.f;
    #pragma unroll
    for (int t = 0; t < 8; t++) {
        v[t].x = __expf(v[t].x - mx); v[t].y = __expf(v[t].y - mx);
        s += v[t].x + v[t].y;
    }
    #pragma unroll
    for (int o = 16; o; o >>= 1) s += __shfl_xor_sync(0xffffffffu, s, o);
    float inv = 1.f / s;
    #pragma unroll
    for (int t = 0; t < 8; t++)
        ph[lane + t*32] = __floats2half2_rn(v[t].x * inv, v[t].y * inv);
    if (lane == 0) g_m[warp] = mx + g_u[warp];
}

// ---------------------------------------------------------------------------
// q2c chain
// ---------------------------------------------------------------------------
__global__ __launch_bounds__(1024) void bmz_kernel()
{
    int b = blockIdx.x, tid = threadIdx.x;
    __shared__ float red[32];
    const float* m = g_m + b*CLEN;
    float mx = fmaxf(m[tid], fmaxf(m[tid+1024], fmaxf(m[tid+2048], m[tid+3072])));
    #pragma unroll
    for (int o = 16; o; o >>= 1) mx = fmaxf(mx, __shfl_xor_sync(0xffffffffu, mx, o));
    if ((tid & 31) == 0) red[tid >> 5] = mx;
    __syncthreads();
    mx = red[0];
    #pragma unroll
    for (int i = 1; i < 32; i++) mx = fmaxf(mx, red[i]);
    __syncthreads();
    float s = __expf(m[tid]-mx) + __expf(m[tid+1024]-mx)
            + __expf(m[tid+2048]-mx) + __expf(m[tid+3072]-mx);
    #pragma unroll
    for (int o = 16; o; o >>= 1) s += __shfl_xor_sync(0xffffffffu, s, o);
    if ((tid & 31) == 0) red[tid >> 5] = s;
    __syncthreads();
    if (tid == 0) {
        float Z = 0.f;
        #pragma unroll
        for (int i = 0; i < 32; i++) Z += red[i];
        g_bm[b] = mx; g_Z[b] = Z;
    }
}

__global__ __launch_bounds__(256) void q2c_part()
{
    const int b = blockIdx.y, p = blockIdx.x, tid = threadIdx.x;
    __shared__ float w[128];
    if (tid < 128) w[tid] = __expf(g_m[b*CLEN + p*128 + tid] - g_bm[b]);
    __syncthreads();
    const float invZ = 1.f / g_Z[b];
    const __half* cb = g_ch + ((size_t)b*CLEN + p*128)*H + tid;
    float acc = 0.f;
    #pragma unroll 8
    for (int i = 0; i < 128; i++) acc = fmaf(w[i], __half2float(cb[(size_t)i*H]), acc);
    g_part[(b*32 + p)*H + tid] = acc * invZ;
}

__global__ __launch_bounds__(256) void q2c_reduce()
{
    int b = blockIdx.x, d = threadIdx.x;
    float s = 0.f;
    #pragma unroll
    for (int p = 0; p < 32; p++) s += g_part[(b*32 + p)*H + d];
    g_q2c[b*H + d] = s;
}

// ---------------------------------------------------------------------------
// GEMM2 (fp16 mma + ldmatrix + 4-stage BK=32, 256 thr, CTA 128x128, occ 2):
// c2q = P @ q + fused epilogue (fp32 c reads, streaming output stores)
// ---------------------------------------------------------------------------
__global__ __launch_bounds__(256,2) void gemm2_f16(
    const float* __restrict__ c, float* __restrict__ out)
{
    extern __shared__ __align__(128) char dsm[];
    const int b  = blockIdx.z, m0 = blockIdx.y*128, n0 = blockIdx.x*128;
    const int tid = threadIdx.x;
    const int lane = tid & 31, wid = tid >> 5;
    const int wm = wid >> 2, wn = wid & 3;
    const int gid = lane >> 2, tig = lane & 3;
    const int cr = tid >> 1;
    const int cc = (tid & 1) * 16;

    const __half* Ag = g_P  + ((size_t)b*CLEN + m0 + cr)*QLEN + cc;
    const __half* Bg = g_qt + ((size_t)b*H    + n0 + cr)*QLEN + cc;
    const uint32_t sbase = (uint32_t)__cvta_generic_to_shared(dsm);
    const uint32_t wOff = (uint32_t)(cr*PITCH + cc)*2u;

    const int rA = lane & 15, cA = (lane & 16) >> 1;
    const int rB = (lane & 7) + ((lane & 16) >> 1), cB = lane & 8;
    const uint32_t offA = (uint32_t)(rA*PITCH + cA)*2u;
    const uint32_t offB = (uint32_t)(rB*PITCH + cB)*2u;

    float acc[4][4][4];
    #pragma unroll
    for (int i = 0; i < 4; i++)
        #pragma unroll
        for (int j = 0; j < 4; j++)
            #pragma unroll
            for (int r = 0; r < 4; r++) acc[i][j][r] = 0.f;

    const int NIT = QLEN/32;   // 16
    #pragma unroll
    for (int p = 0; p < 3; p++) {
        const uint32_t sa = sbase + p*TILEB + wOff;
        const uint32_t sb = sbase + BOFF + p*TILEB + wOff;
        CPA16(sa, Ag + p*32); CPA16(sa + 16u, Ag + p*32 + 8);
        CPA16(sb, Bg + p*32); CPA16(sb + 16u, Bg + p*32 + 8);
        CPCOMMIT();
    }

    for (int i = 0; i < NIT; i++) {
        if (i < NIT-2)      { CPWAIT2(); }
        else if (i == NIT-2){ CPWAIT1(); }
        else                { CPWAIT0(); }
        __syncthreads();
        const int st = i & 3;
        const uint32_t aBase = sbase + st*TILEB + (uint32_t)(wm*64)*PITCH*2u + offA;
        const uint32_t bBase = sbase + BOFF + st*TILEB + (uint32_t)(wn*32)*PITCH*2u + offB;
        #pragma unroll
        for (int ks = 0; ks < 32; ks += 16) {
            uint32_t a[4][4], bf[4][2];
            #pragma unroll
            for (int mt = 0; mt < 4; mt++)
                LDSM4(a[mt][0], a[mt][1], a[mt][2], a[mt][3],
                      aBase + (uint32_t)(mt*16)*PITCH*2u + ks*2u);
            #pragma unroll
            for (int p = 0; p < 2; p++)
                LDSM4(bf[2*p][0], bf[2*p][1], bf[2*p+1][0], bf[2*p+1][1],
                      bBase + (uint32_t)(p*16)*PITCH*2u + ks*2u);
            #pragma unroll
            for (int mt = 0; mt < 4; mt++)
                #pragma unroll
                for (int nt = 0; nt < 4; nt++)
                    mma_f16(acc[mt][nt], a[mt], bf[nt]);
        }
        if (i + 3 < NIT) {
            const int kc = (i+3)*32, s2 = (i+3) & 3;
            const uint32_t sa = sbase + s2*TILEB + wOff;
            const uint32_t sb = sbase + BOFF + s2*TILEB + wOff;
            CPA16(sa, Ag + kc); CPA16(sa + 16u, Ag + kc + 8);
            CPA16(sb, Bg + kc); CPA16(sb + 16u, Bg + kc + 8);
            CPCOMMIT();
        }
    }

    // fused epilogue: out = [c | c2q | c*c2q | c*q2c], streaming stores
    const int nbase = n0 + wn*32;
    float2 gv[4];
    #pragma unroll
    for (int nt = 0; nt < 4; nt++)
        gv[nt] = *(const float2*)&g_q2c[b*H + nbase + nt*8 + 2*tig];
    #pragma unroll
    for (int mt = 0; mt < 4; mt++)
        #pragma unroll
        for (int r = 0; r < 2; r++) {
            int row = m0 + wm*64 + mt*16 + gid + 8*r;
            const float* crow = c + ((size_t)b*CLEN + row)*H;
            float* orow = out + ((size_t)b*CLEN + row)*(4*H);
            #pragma unroll
            for (int nt = 0; nt < 4; nt++) {
                int col = nbase + nt*8 + 2*tig;
                float2 cv = *(const float2*)&crow[col];
                float2 av = make_float2(acc[mt][nt][2*r], acc[mt][nt][2*r+1]);
                STGCS2(&orow[col],       cv.x,        cv.y);
                STGCS2(&orow[H + col],   av.x,        av.y);
                STGCS2(&orow[2*H + col], cv.x*av.x,   cv.y*av.y);
                STGCS2(&orow[3*H + col], cv.x*gv[nt].x, cv.y*gv[nt].y);
            }
        }
}

// ---------------------------------------------------------------------------
extern "C" void kernel_launch(void* const* d_in, const int* in_sizes, int n_in,
                              void* d_out, int out_size)
{
    const float* c    = (const float*)d_in[0];
    const float* q    = (const float*)d_in[1];
    const float* w_c  = (const float*)d_in[2];
    const float* b_c  = (const float*)d_in[3];
    const float* w_q  = (const float*)d_in[4];
    const float* b_q  = (const float*)d_in[5];
    const float* w_cq = (const float*)d_in[6];
    const float* b_cq = (const float*)d_in[7];
    float* out = (float*)d_out;

    cudaFuncSetAttribute(gemm1_f16, cudaFuncAttributeMaxDynamicSharedMemorySize, SMEMSZ);
    cudaFuncSetAttribute(gemm2_f16, cudaFuncAttributeMaxDynamicSharedMemorySize, SMEMSZ);

    {   // fused fp16 conversions + row dots
        int warps = B_*CLEN + B_*QLEN;
        prep_uv<<<(warps*32 + 255)/256, 256>>>(c, q, w_c, b_c, w_q, b_q, w_cq, b_cq);
    }
    {   // q^T fp16 for gemm2
        dim3 grid(QLEN/32, H/32, B_);
        qtrans_kernel<<<grid, dim3(32, 8)>>>(q);
    }
    {   // S = c.(q*w_cq)^T + v
        dim3 grid(QLEN/128, CLEN/128, B_);
        gemm1_f16<<<grid, 512, SMEMSZ>>>();
    }
    {   // row softmax -> fp16 probs
        int warps = B_*CLEN;
        softmax_kernel<<<(warps*32 + 255)/256, 256>>>();
    }
    bmz_kernel<<<B_, 1024>>>();
    {
        dim3 grid(32, B_);
        q2c_part<<<grid, 256>>>();
    }
    q2c_reduce<<<B_, 256>>>();
    {   // c2q + fused output (128x128 tiles, occupancy 2, streaming stores)
        dim3 grid(H/128, CLEN/128, B_);
        gemm2_f16<<<grid, 256, SMEMSZ>>>(c, out);
    }
}

// round 17
// speedup vs baseline: 1.0729x; 1.0263x over previous
#include <cuda_runtime.h>
#include <cuda_fp16.h>
#include <math.h>
#include <stdint.h>

#define B_   16
#define CLEN 4096
#define QLEN 512
#define H    256

// ---- scratch (device globals; allocation-free) ----
__device__ __align__(128) __half g_S [(size_t)B_*CLEN*QLEN];   // logits S (fp16)
__device__ __align__(128) __half g_P [(size_t)B_*CLEN*QLEN];   // probs fp16
__device__ __align__(128) __half g_ch[(size_t)B_*CLEN*H];      // c fp16
__device__ __align__(128) __half g_qsh[B_*QLEN*H];             // (q*w_cq) fp16
__device__ __align__(128) __half g_qt[B_*H*QLEN];              // q^T fp16 [b][d][j]
__device__ float g_u[B_*CLEN];
__device__ float g_v[B_*QLEN];
__device__ float g_m[B_*CLEN];
__device__ float g_bm[B_];
__device__ float g_Z[B_];
__device__ float g_part[B_*32*H];
__device__ float g_q2c[B_*H];

#define CPA16(s,g)  asm volatile("cp.async.cg.shared.global [%0], [%1], 16;\n" :: "r"(s), "l"(g))
#define CPCOMMIT()  asm volatile("cp.async.commit_group;\n")
#define CPWAIT0()   asm volatile("cp.async.wait_group 0;\n")
#define CPWAIT1()   asm volatile("cp.async.wait_group 1;\n")
#define CPWAIT2()   asm volatile("cp.async.wait_group 2;\n")

#define LDSM4(r0,r1,r2,r3,addr) \
    asm volatile("ldmatrix.sync.aligned.m8n8.x4.shared.b16 {%0,%1,%2,%3}, [%4];" \
        : "=r"(r0),"=r"(r1),"=r"(r2),"=r"(r3) : "r"(addr))

// streaming (evict-first) 8-byte store
#define STGCS2(ptr, x, y) \
    asm volatile("st.global.cs.v2.f32 [%0], {%1,%2};" :: "l"(ptr), "f"(x), "f"(y) : "memory")

__device__ __forceinline__ void mma_f16(float* d, const uint32_t* a, const uint32_t* b){
    asm volatile("mma.sync.aligned.m16n8k16.row.col.f32.f16.f16.f32 "
        "{%0,%1,%2,%3}, {%4,%5,%6,%7}, {%8,%9}, {%0,%1,%2,%3};"
        : "+f"(d[0]),"+f"(d[1]),"+f"(d[2]),"+f"(d[3])
        : "r"(a[0]),"r"(a[1]),"r"(a[2]),"r"(a[3]), "r"(b[0]),"r"(b[1]));
}

// gemm1 tile geometry: CTA 128x128, BK=32, pitch 40 halves, 4 stages
#define PITCH   40
#define TILEB   10240u            // 128*40*2 bytes per operand per stage
#define BOFF    40960u            // B tiles start after 4 A stages
#define SMEMSZ  81920             // 2 ops * 4 stages * TILEB

// gemm2 tile geometry: CTA 64x256, BK=32, 3 stages
#define G2_TA   5120u             // 64*40*2
#define G2_TB   20480u            // 256*40*2
#define G2_BOFF 15360u            // after 3 A stages
#define SMEMSZ2 76800             // 3*(5120+20480)

// ---------------------------------------------------------------------------
// prep_uv (fused): warp-per-row.
// ---------------------------------------------------------------------------
__global__ __launch_bounds__(256) void prep_uv(
    const float* __restrict__ c, const float* __restrict__ q,
    const float* __restrict__ w_c, const float* __restrict__ b_c,
    const float* __restrict__ w_q, const float* __restrict__ b_q,
    const float* __restrict__ w_cq, const float* __restrict__ b_cq)
{
    int warp = (blockIdx.x * blockDim.x + threadIdx.x) >> 5;
    int lane = threadIdx.x & 31;
    if (warp < B_ * CLEN) {
        const float4* row = (const float4*)(c + (size_t)warp * H);
        uint2* dst = (uint2*)(g_ch + (size_t)warp * H);
        float s = 0.f;
        #pragma unroll
        for (int t = 0; t < 2; t++) {
            int idx = lane + t*32;
            float4 x = row[idx];
            float4 wv = ((const float4*)w_c)[idx];
            s += x.x*wv.x + x.y*wv.y + x.z*wv.z + x.w*wv.w;
            union { __half2 h2[2]; uint2 u; } tt;
            tt.h2[0] = __floats2half2_rn(x.x, x.y);
            tt.h2[1] = __floats2half2_rn(x.z, x.w);
            dst[idx] = tt.u;
        }
        #pragma unroll
        for (int o = 16; o; o >>= 1) s += __shfl_xor_sync(0xffffffffu, s, o);
        if (lane == 0) g_u[warp] = s + b_c[0];
    } else {
        int r = warp - B_ * CLEN;
        if (r < B_ * QLEN) {
            const float4* row = (const float4*)(q + (size_t)r * H);
            uint2* dst = (uint2*)(g_qsh + (size_t)r * H);
            float s = 0.f;
            #pragma unroll
            for (int t = 0; t < 2; t++) {
                int idx = lane + t*32;
                float4 x = row[idx];
                float4 wq = ((const float4*)w_q)[idx];
                float4 wm = ((const float4*)w_cq)[idx];
                s += x.x*wq.x + x.y*wq.y + x.z*wq.z + x.w*wq.w;
                union { __half2 h2[2]; uint2 u; } tt;
                tt.h2[0] = __floats2half2_rn(x.x*wm.x, x.y*wm.y);
                tt.h2[1] = __floats2half2_rn(x.z*wm.z, x.w*wm.w);
                dst[idx] = tt.u;
            }
            #pragma unroll
            for (int o = 16; o; o >>= 1) s += __shfl_xor_sync(0xffffffffu, s, o);
            if (lane == 0) g_v[r] = s + b_q[0] + b_cq[0];
        }
    }
}

// ---------------------------------------------------------------------------
// qtrans: q[b][j][d] fp32 -> g_qt[b][d][j] fp16
// ---------------------------------------------------------------------------
__global__ void qtrans_kernel(const float* __restrict__ q)
{
    __shared__ float tile[32][33];
    const int j0 = blockIdx.x * 32, d0 = blockIdx.y * 32, b = blockIdx.z;
    const int tx = threadIdx.x, ty = threadIdx.y;   // 32 x 8
    #pragma unroll
    for (int r = 0; r < 4; r++)
        tile[ty + 8*r][tx] = q[((size_t)b*QLEN + j0 + ty + 8*r)*H + d0 + tx];
    __syncthreads();
    #pragma unroll
    for (int r = 0; r < 4; r++) {
        int d = d0 + ty + 8*r, j = j0 + tx;
        g_qt[((size_t)b*H + d)*QLEN + j] = __float2half_rn(tile[tx][ty + 8*r]);
    }
}

// ---------------------------------------------------------------------------
// GEMM1 (fp16 mma, 512 thr, warp 32x32, 4-stage BK=32): S = c.(q*w_cq)^T + v
// ---------------------------------------------------------------------------
__global__ __launch_bounds__(512,2) void gemm1_f16()
{
    extern __shared__ __align__(128) char dsm[];
    const int b  = blockIdx.z, m0 = blockIdx.y*128, n0 = blockIdx.x*128;
    const int tid = threadIdx.x;
    const int lane = tid & 31, wid = tid >> 5;
    const int wm = wid >> 2, wn = wid & 3;
    const int gid = lane >> 2, tig = lane & 3;
    const int cr = tid >> 2;
    const int cc = (tid & 3) * 8;

    const __half* Ag = g_ch  + ((size_t)b*CLEN + m0 + cr)*H + cc;
    const __half* Bg = g_qsh + ((size_t)b*QLEN + n0 + cr)*H + cc;
    const uint32_t sbase = (uint32_t)__cvta_generic_to_shared(dsm);
    const uint32_t wOff = (uint32_t)(cr*PITCH + cc)*2u;

    const int rA = lane & 15, cA = (lane & 16) >> 1;
    const int rB = (lane & 7) + ((lane & 16) >> 1), cB = lane & 8;
    const uint32_t offA = (uint32_t)(rA*PITCH + cA)*2u;
    const uint32_t offB = (uint32_t)(rB*PITCH + cB)*2u;

    float acc[2][4][4];
    #pragma unroll
    for (int i = 0; i < 2; i++)
        #pragma unroll
        for (int j = 0; j < 4; j++)
            #pragma unroll
            for (int r = 0; r < 4; r++) acc[i][j][r] = 0.f;

    const int NIT = H/32;   // 8
    #pragma unroll
    for (int p = 0; p < 3; p++) {
        CPA16(sbase + p*TILEB + wOff,        Ag + p*32);
        CPA16(sbase + BOFF + p*TILEB + wOff, Bg + p*32);
        CPCOMMIT();
    }

    for (int i = 0; i < NIT; i++) {
        if (i < NIT-2)      { CPWAIT2(); }
        else if (i == NIT-2){ CPWAIT1(); }
        else                { CPWAIT0(); }
        __syncthreads();
        const int st = i & 3;
        const uint32_t aBase = sbase + st*TILEB + (uint32_t)(wm*32)*PITCH*2u + offA;
        const uint32_t bBase = sbase + BOFF + st*TILEB + (uint32_t)(wn*32)*PITCH*2u + offB;
        #pragma unroll
        for (int ks = 0; ks < 32; ks += 16) {
            uint32_t a[2][4], bf[4][2];
            #pragma unroll
            for (int mt = 0; mt < 2; mt++)
                LDSM4(a[mt][0], a[mt][1], a[mt][2], a[mt][3],
                      aBase + (uint32_t)(mt*16)*PITCH*2u + ks*2u);
            #pragma unroll
            for (int p = 0; p < 2; p++)
                LDSM4(bf[2*p][0], bf[2*p][1], bf[2*p+1][0], bf[2*p+1][1],
                      bBase + (uint32_t)(p*16)*PITCH*2u + ks*2u);
            #pragma unroll
            for (int mt = 0; mt < 2; mt++)
                #pragma unroll
                for (int nt = 0; nt < 4; nt++)
                    mma_f16(acc[mt][nt], a[mt], bf[nt]);
        }
        if (i + 3 < NIT) {
            const int kc = (i+3)*32, s2 = (i+3) & 3;
            CPA16(sbase + s2*TILEB + wOff,        Ag + kc);
            CPA16(sbase + BOFF + s2*TILEB + wOff, Bg + kc);
            CPCOMMIT();
        }
    }

    // epilogue: +v, write S fp16
    const float* vb = g_v + b*QLEN + n0 + wn*32;
    float2 vv[4];
    #pragma unroll
    for (int nt = 0; nt < 4; nt++) vv[nt] = *(const float2*)&vb[nt*8 + 2*tig];
    #pragma unroll
    for (int mt = 0; mt < 2; mt++)
        #pragma unroll
        for (int r = 0; r < 2; r++) {
            int row = m0 + wm*32 + mt*16 + gid + 8*r;
            __half2* p = (__half2*)(g_S + ((size_t)b*CLEN + row)*QLEN + n0 + wn*32);
            #pragma unroll
            for (int nt = 0; nt < 4; nt++)
                p[nt*4 + tig] = __floats2half2_rn(acc[mt][nt][2*r]   + vv[nt].x,
                                                  acc[mt][nt][2*r+1] + vv[nt].y);
        }
}

// ---------------------------------------------------------------------------
// softmax over j (512): read S fp16, write probs fp16; g_m = rowmax + u
// ---------------------------------------------------------------------------
__global__ __launch_bounds__(256) void softmax_kernel()
{
    int warp = (blockIdx.x * blockDim.x + threadIdx.x) >> 5;
    if (warp >= B_ * CLEN) return;
    int lane = threadIdx.x & 31;
    const __half2* row = (const __half2*)(g_S + (size_t)warp * QLEN);
    __half2* ph = (__half2*)(g_P + (size_t)warp * QLEN);

    float2 v[8];
    float mx = -3.402823466e38f;
    #pragma unroll
    for (int t = 0; t < 8; t++) {
        v[t] = __half22float2(row[lane + t*32]);
        mx = fmaxf(mx, fmaxf(v[t].x, v[t].y));
    }
    #pragma unroll
    for (int o = 16; o; o >>= 1) mx = fmaxf(mx, __shfl_xor_sync(0xffffffffu, mx, o));
    float s = 0.f;
    #pragma unroll
    for (int t = 0; t < 8; t++) {
        v[t].x = __expf(v[t].x - mx); v[t].y = __expf(v[t].y - mx);
        s += v[t].x + v[t].y;
    }
    #pragma unroll
    for (int o = 16; o; o >>= 1) s += __shfl_xor_sync(0xffffffffu, s, o);
    float inv = 1.f / s;
    #pragma unroll
    for (int t = 0; t < 8; t++)
        ph[lane + t*32] = __floats2half2_rn(v[t].x * inv, v[t].y * inv);
    if (lane == 0) g_m[warp] = mx + g_u[warp];
}

// ---------------------------------------------------------------------------
// q2c chain
// ---------------------------------------------------------------------------
__global__ __launch_bounds__(1024) void bmz_kernel()
{
    int b = blockIdx.x, tid = threadIdx.x;
    __shared__ float red[32];
    const float* m = g_m + b*CLEN;
    float mx = fmaxf(m[tid], fmaxf(m[tid+1024], fmaxf(m[tid+2048], m[tid+3072])));
    #pragma unroll
    for (int o = 16; o; o >>= 1) mx = fmaxf(mx, __shfl_xor_sync(0xffffffffu, mx, o));
    if ((tid & 31) == 0) red[tid >> 5] = mx;
    __syncthreads();
    mx = red[0];
    #pragma unroll
    for (int i = 1; i < 32; i++) mx = fmaxf(mx, red[i]);
    __syncthreads();
    float s = __expf(m[tid]-mx) + __expf(m[tid+1024]-mx)
            + __expf(m[tid+2048]-mx) + __expf(m[tid+3072]-mx);
    #pragma unroll
    for (int o = 16; o; o >>= 1) s += __shfl_xor_sync(0xffffffffu, s, o);
    if ((tid & 31) == 0) red[tid >> 5] = s;
    __syncthreads();
    if (tid == 0) {
        float Z = 0.f;
        #pragma unroll
        for (int i = 0; i < 32; i++) Z += red[i];
        g_bm[b] = mx; g_Z[b] = Z;
    }
}

__global__ __launch_bounds__(256) void q2c_part()
{
    const int b = blockIdx.y, p = blockIdx.x, tid = threadIdx.x;
    __shared__ float w[128];
    if (tid < 128) w[tid] = __expf(g_m[b*CLEN + p*128 + tid] - g_bm[b]);
    __syncthreads();
    const float invZ = 1.f / g_Z[b];
    const __half* cb = g_ch + ((size_t)b*CLEN + p*128)*H + tid;
    float acc = 0.f;
    #pragma unroll 8
    for (int i = 0; i < 128; i++) acc = fmaf(w[i], __half2float(cb[(size_t)i*H]), acc);
    g_part[(b*32 + p)*H + tid] = acc * invZ;
}

__global__ __launch_bounds__(256) void q2c_reduce()
{
    int b = blockIdx.x, d = threadIdx.x;
    float s = 0.f;
    #pragma unroll
    for (int p = 0; p < 32; p++) s += g_part[(b*32 + p)*H + d];
    g_q2c[b*H + d] = s;
}

// ---------------------------------------------------------------------------
// GEMM2 (fp16 mma, 256 thr, CTA 64x256, warp 32x64, 3-stage BK=32, occ 2):
// c2q = P @ q + fused epilogue (fp32 c reads, streaming output stores)
// P is read ONCE (full H per CTA).
// ---------------------------------------------------------------------------
__global__ __launch_bounds__(256,2) void gemm2_f16(
    const float* __restrict__ c, float* __restrict__ out)
{
    extern __shared__ __align__(128) char dsm[];
    const int b  = blockIdx.y, m0 = blockIdx.x*64;
    const int tid = threadIdx.x;
    const int lane = tid & 31, wid = tid >> 5;
    const int wm = wid >> 2, wn = wid & 3;      // 2 x 4 warps; warp tile 32x64
    const int gid = lane >> 2, tig = lane & 3;
    const int cr = tid >> 2;                    // 0..63
    const int cc = (tid & 3) * 8;               // 0/8/16/24

    const __half* Ag = g_P  + ((size_t)b*CLEN + m0 + cr)*QLEN + cc;
    const __half* Bg = g_qt + ((size_t)b*H + cr)*QLEN + cc;    // rows cr, +64, +128, +192
    const uint32_t sbase = (uint32_t)__cvta_generic_to_shared(dsm);
    const uint32_t wA = (uint32_t)(cr*PITCH + cc)*2u;
    const uint32_t wB = (uint32_t)(cr*PITCH + cc)*2u;

    const int rA = lane & 15, cA = (lane & 16) >> 1;
    const int rB = (lane & 7) + ((lane & 16) >> 1), cB = lane & 8;
    const uint32_t offA = (uint32_t)(rA*PITCH + cA)*2u;
    const uint32_t offB = (uint32_t)(rB*PITCH + cB)*2u;

    float acc[2][8][4];
    #pragma unroll
    for (int i = 0; i < 2; i++)
        #pragma unroll
        for (int j = 0; j < 8; j++)
            #pragma unroll
            for (int r = 0; r < 4; r++) acc[i][j][r] = 0.f;

    const int NIT = QLEN/32;   // 16
    // prologue: stages 0,1
    #pragma unroll
    for (int p = 0; p < 2; p++) {
        CPA16(sbase + p*G2_TA + wA, Ag + p*32);
        #pragma unroll
        for (int k = 0; k < 4; k++)
            CPA16(sbase + G2_BOFF + p*G2_TB + wB + (uint32_t)(k*64)*PITCH*2u,
                  Bg + (size_t)(k*64)*QLEN + p*32);
        CPCOMMIT();
    }

    for (int i = 0; i < NIT; i++) {
        if (i == NIT-1) { CPWAIT0(); } else { CPWAIT1(); }
        __syncthreads();
        const int st = i % 3;
        const uint32_t aBase = sbase + st*G2_TA + (uint32_t)(wm*32)*PITCH*2u + offA;
        const uint32_t bBase = sbase + G2_BOFF + st*G2_TB + (uint32_t)(wn*64)*PITCH*2u + offB;
        #pragma unroll
        for (int ks = 0; ks < 32; ks += 16) {
            uint32_t a[2][4], bf[8][2];
            #pragma unroll
            for (int mt = 0; mt < 2; mt++)
                LDSM4(a[mt][0], a[mt][1], a[mt][2], a[mt][3],
                      aBase + (uint32_t)(mt*16)*PITCH*2u + ks*2u);
            #pragma unroll
            for (int p = 0; p < 4; p++)
                LDSM4(bf[2*p][0], bf[2*p][1], bf[2*p+1][0], bf[2*p+1][1],
                      bBase + (uint32_t)(p*16)*PITCH*2u + ks*2u);
            #pragma unroll
            for (int mt = 0; mt < 2; mt++)
                #pragma unroll
                for (int nt = 0; nt < 8; nt++)
                    mma_f16(acc[mt][nt], a[mt], bf[nt]);
        }
        if (i + 2 < NIT) {
            const int kc = (i+2)*32, s2 = (i+2) % 3;
            CPA16(sbase + s2*G2_TA + wA, Ag + kc);
            #pragma unroll
            for (int k = 0; k < 4; k++)
                CPA16(sbase + G2_BOFF + s2*G2_TB + wB + (uint32_t)(k*64)*PITCH*2u,
                      Bg + (size_t)(k*64)*QLEN + kc);
            CPCOMMIT();
        }
    }

    // fused epilogue: out = [c | c2q | c*c2q | c*q2c]
    const int nbase = wn*64;
    float2 gv[8];
    #pragma unroll
    for (int nt = 0; nt < 8; nt++)
        gv[nt] = *(const float2*)&g_q2c[b*H + nbase + nt*8 + 2*tig];
    #pragma unroll
    for (int mt = 0; mt < 2; mt++)
        #pragma unroll
        for (int r = 0; r < 2; r++) {
            int row = m0 + wm*32 + mt*16 + gid + 8*r;
            const float* crow = c + ((size_t)b*CLEN + row)*H;
            float* orow = out + ((size_t)b*CLEN + row)*(4*H);
            #pragma unroll
            for (int nt = 0; nt < 8; nt++) {
                int col = nbase + nt*8 + 2*tig;
                float2 cv = *(const float2*)&crow[col];
                float2 av = make_float2(acc[mt][nt][2*r], acc[mt][nt][2*r+1]);
                STGCS2(&orow[col],       cv.x,        cv.y);
                STGCS2(&orow[H + col],   av.x,        av.y);
                STGCS2(&orow[2*H + col], cv.x*av.x,   cv.y*av.y);
                STGCS2(&orow[3*H + col], cv.x*gv[nt].x, cv.y*gv[nt].y);
            }
        }
}

// ---------------------------------------------------------------------------
extern "C" void kernel_launch(void* const* d_in, const int* in_sizes, int n_in,
                              void* d_out, int out_size)
{
    const float* c    = (const float*)d_in[0];
    const float* q    = (const float*)d_in[1];
    const float* w_c  = (const float*)d_in[2];
    const float* b_c  = (const float*)d_in[3];
    const float* w_q  = (const float*)d_in[4];
    const float* b_q  = (const float*)d_in[5];
    const float* w_cq = (const float*)d_in[6];
    const float* b_cq = (const float*)d_in[7];
    float* out = (float*)d_out;

    cudaFuncSetAttribute(gemm1_f16, cudaFuncAttributeMaxDynamicSharedMemorySize, SMEMSZ);
    cudaFuncSetAttribute(gemm2_f16, cudaFuncAttributeMaxDynamicSharedMemorySize, SMEMSZ2);

    {   // fused fp16 conversions + row dots
        int warps = B_*CLEN + B_*QLEN;
        prep_uv<<<(warps*32 + 255)/256, 256>>>(c, q, w_c, b_c, w_q, b_q, w_cq, b_cq);
    }
    {   // q^T fp16 for gemm2
        dim3 grid(QLEN/32, H/32, B_);
        qtrans_kernel<<<grid, dim3(32, 8)>>>(q);
    }
    {   // S = c.(q*w_cq)^T + v
        dim3 grid(QLEN/128, CLEN/128, B_);
        gemm1_f16<<<grid, 512, SMEMSZ>>>();
    }
    {   // row softmax -> fp16 probs
        int warps = B_*CLEN;
        softmax_kernel<<<(warps*32 + 255)/256, 256>>>();
    }
    bmz_kernel<<<B_, 1024>>>();
    {
        dim3 grid(32, B_);
        q2c_part<<<grid, 256>>>();
    }
    q2c_reduce<<<B_, 256>>>();
    {   // c2q + fused output (64x256 tiles, occ 2, single P pass)
        dim3 grid(CLEN/64, B_);
        gemm2_f16<<<grid, 256, SMEMSZ2>>>(c, out);
    }
}